// round 2
// baseline (speedup 1.0000x reference)
#include <cuda_runtime.h>
#include <cuda_bf16.h>
#include <cstdint>

// Problem shape (fixed by dataset)
#define BB 8
#define SS 2048
#define DD 1024
#define OO 1024
#define LCH 256           // scan chunk length
#define NCH (SS / LCH)    // 8 chunks

// ---------------- device scratch (no allocations allowed) ----------------
__device__ float          g_carry[BB * NCH * DD];                 // 256 KB
__device__ __nv_bfloat16  g_hs_hi[(size_t)BB * SS * DD];          // 32 MB
__device__ __nv_bfloat16  g_hs_lo[(size_t)BB * SS * DD];          // 32 MB
__device__ __nv_bfloat16  g_bct_hi[(size_t)OO * DD];              // 2 MB  (BC^T hi)
__device__ __nv_bfloat16  g_bct_lo[(size_t)OO * DD];              // 2 MB  (BC^T lo)

// ---------------- helpers --------------------------------------------------
__device__ __forceinline__ uint32_t smem_u32(const void* p) {
    uint32_t a;
    asm("{ .reg .u64 t; cvta.to.shared.u64 t, %1; cvt.u32.u64 %0, t; }"
        : "=r"(a) : "l"(p));
    return a;
}

#define SW128(off) ((off) ^ (((off) >> 3) & 0x70))

#define CP_ASYNC_16(dst_smem, src_gmem) \
    asm volatile("cp.async.cg.shared.global [%0], [%1], 16;" \
                 :: "r"(dst_smem), "l"(src_gmem) : "memory")
#define CP_COMMIT() asm volatile("cp.async.commit_group;" ::: "memory")
#define CP_WAIT_GROUP(n) asm volatile("cp.async.wait_group %0;" :: "n"(n) : "memory")

#define LDSM_X4(r0, r1, r2, r3, addr) \
    asm volatile("ldmatrix.sync.aligned.m8n8.x4.shared.b16 {%0,%1,%2,%3}, [%4];" \
                 : "=r"(r0), "=r"(r1), "=r"(r2), "=r"(r3) : "r"(addr))

#define MMA_BF16(c, a, b) \
    asm volatile("mma.sync.aligned.m16n8k16.row.col.f32.bf16.bf16.f32 " \
                 "{%0,%1,%2,%3}, {%4,%5,%6,%7}, {%8,%9}, {%0,%1,%2,%3};" \
                 : "+f"((c)[0]), "+f"((c)[1]), "+f"((c)[2]), "+f"((c)[3]) \
                 : "r"((a)[0]), "r"((a)[1]), "r"((a)[2]), "r"((a)[3]), \
                   "r"((b)[0]), "r"((b)[1]))

// ---------------- Kernel 1: per-chunk carries -----------------------------
__global__ void scan_carry_kernel(const float* __restrict__ x,
                                  const float* __restrict__ A) {
    int idx = blockIdx.x * blockDim.x + threadIdx.x;   // B*NCH*DD threads
    int d = idx & (DD - 1);
    int chunk = (idx >> 10) & (NCH - 1);
    int b = idx >> 13;
    float a = A[d];
    const float* xp = x + ((size_t)(b * SS + chunk * LCH)) * DD + d;
    float h = 0.0f;
#pragma unroll 4
    for (int i = 0; i < LCH; i++) {
        h = fmaf(h, a, xp[(size_t)i * DD]);
    }
    g_carry[idx] = h;   // idx == (b*NCH + chunk)*DD + d
}

// ---------------- Kernel 2: carry-corrected emit (fp32 -> bf16 hi/lo) -----
__global__ void scan_emit_kernel(const float* __restrict__ x,
                                 const float* __restrict__ A) {
    int idx = blockIdx.x * blockDim.x + threadIdx.x;
    int d = idx & (DD - 1);
    int chunk = (idx >> 10) & (NCH - 1);
    int b = idx >> 13;
    float a = A[d];
    float aL = a;
#pragma unroll
    for (int s = 0; s < 8; s++) aL *= aL;      // a^256
    float h = 0.0f;
    for (int j = 0; j < chunk; j++) {
        h = fmaf(h, aL, g_carry[(b * NCH + j) * DD + d]);
    }
    size_t base = ((size_t)(b * SS + chunk * LCH)) * DD + d;
#pragma unroll 4
    for (int i = 0; i < LCH; i++) {
        h = fmaf(h, a, x[base + (size_t)i * DD]);
        __nv_bfloat16 hi = __float2bfloat16_rn(h);
        float lo = h - __bfloat162float(hi);
        g_hs_hi[base + (size_t)i * DD] = hi;
        g_hs_lo[base + (size_t)i * DD] = __float2bfloat16_rn(lo);
    }
}

// ---------------- Kernel 3: BC [D,O] -> BC^T hi/lo [O,D] ------------------
__global__ void bc_transpose_split_kernel(const float* __restrict__ bc) {
    __shared__ float tile[32][33];
    int o0 = blockIdx.x * 32;
    int d0 = blockIdx.y * 32;
    int tx = threadIdx.x, ty = threadIdx.y;    // 32 x 8
#pragma unroll
    for (int j = 0; j < 32; j += 8) {
        tile[ty + j][tx] = bc[(size_t)(d0 + ty + j) * OO + o0 + tx];
    }
    __syncthreads();
#pragma unroll
    for (int j = 0; j < 32; j += 8) {
        float v = tile[tx][ty + j];            // = BC[d0+tx][o0+ty+j]
        size_t oi = (size_t)(o0 + ty + j) * DD + d0 + tx;
        __nv_bfloat16 hi = __float2bfloat16_rn(v);
        g_bct_hi[oi] = hi;
        g_bct_lo[oi] = __float2bfloat16_rn(v - __bfloat162float(hi));
    }
}

// ---------------- Kernel 4: pipelined HMMA bf16x3 GEMM --------------------
// out[r, n] = sum_k hs[r, k] * BC[k, n],  r = b*S+s (16384 rows)
#define TM 128
#define TN 128
#define KT 64
#define NKC (DD / KT)        // 16 K-chunks
#define STAGES 3
#define TILE_BYTES (128 * 128)          // one operand tile (128 rows x 128B)
#define STAGE_BYTES (4 * TILE_BYTES)    // A_hi, A_lo, B_hi, B_lo  = 64 KB
#define SM_GEMM (STAGES * STAGE_BYTES)  // 192 KB

// issue one stage's cp.asyncs (4096 x 16B chunks across 256 threads)
__device__ __forceinline__ void load_stage(uint32_t stage_base, int m0, int n0,
                                           int kc, int tid) {
    int k0 = kc * KT;
#pragma unroll
    for (int i = 0; i < 16; i++) {
        int c = i * 256 + tid;          // 0..4095 ; tile uniform per i
        int tile = c >> 10;             // 0:A_hi 1:A_lo 2:B_hi 3:B_lo
        int rem = c & 1023;
        int row = rem >> 3;
        int ch = rem & 7;
        uint32_t soff = SW128((uint32_t)(row * 128 + ch * 16));
        uint32_t daddr = stage_base + tile * TILE_BYTES + soff;
        const __nv_bfloat16* gp;
        if (tile == 0)      gp = g_hs_hi  + (size_t)(m0 + row) * DD + k0 + ch * 8;
        else if (tile == 1) gp = g_hs_lo  + (size_t)(m0 + row) * DD + k0 + ch * 8;
        else if (tile == 2) gp = g_bct_hi + (size_t)(n0 + row) * DD + k0 + ch * 8;
        else                gp = g_bct_lo + (size_t)(n0 + row) * DD + k0 + ch * 8;
        CP_ASYNC_16(daddr, gp);
    }
}

__global__ __launch_bounds__(256, 1)
void gemm_bf16x3_kernel(float* __restrict__ out) {
    extern __shared__ __align__(1024) char smem[];
    uint32_t sb = smem_u32(smem);
    int tid = threadIdx.x;
    int wid = tid >> 5;
    int lane = tid & 31;
    int wm = wid & 3;           // 4 warps along M
    int wn = wid >> 2;          // 2 warps along N
    int m0 = blockIdx.x * TM;
    int n0 = blockIdx.y * TN;

    float acc[2][8][4];
#pragma unroll
    for (int mi = 0; mi < 2; mi++)
#pragma unroll
        for (int ni = 0; ni < 8; ni++)
#pragma unroll
            for (int c = 0; c < 4; c++) acc[mi][ni][c] = 0.0f;

    // prologue: fill STAGES-1 stages
#pragma unroll
    for (int s = 0; s < STAGES - 1; s++) {
        load_stage(sb + s * STAGE_BYTES, m0, n0, s, tid);
        CP_COMMIT();
    }

    // precomputed ldmatrix intra-tile offsets
    int a_row = wm * 32 + (lane & 15);
    int a_chb = ((lane >> 4) & 1) * 16;
    int b_row = wn * 64 + ((lane >> 4) & 1) * 8 + (lane & 7);
    int b_chb = ((lane >> 3) & 1) * 16;

    for (int kc = 0; kc < NKC; kc++) {
        CP_WAIT_GROUP(1);
        __syncthreads();
        if (kc + STAGES - 1 < NKC) {
            load_stage(sb + ((kc + STAGES - 1) % STAGES) * STAGE_BYTES,
                       m0, n0, kc + STAGES - 1, tid);
            CP_COMMIT();
        }

        uint32_t st = sb + (kc % STAGES) * STAGE_BYTES;
        uint32_t s_ahi = st;
        uint32_t s_alo = st + TILE_BYTES;
        uint32_t s_bhi = st + 2 * TILE_BYTES;
        uint32_t s_blo = st + 3 * TILE_BYTES;

#pragma unroll
        for (int ks = 0; ks < KT / 16; ks++) {
            uint32_t a_hi[2][4], a_lo[2][4];
            uint32_t b_hi[8][2], b_lo[8][2];
#pragma unroll
            for (int mi = 0; mi < 2; mi++) {
                uint32_t off = SW128((uint32_t)((a_row + mi * 16) * 128 + ks * 32 + a_chb));
                LDSM_X4(a_hi[mi][0], a_hi[mi][1], a_hi[mi][2], a_hi[mi][3], s_ahi + off);
                LDSM_X4(a_lo[mi][0], a_lo[mi][1], a_lo[mi][2], a_lo[mi][3], s_alo + off);
            }
#pragma unroll
            for (int p = 0; p < 4; p++) {
                uint32_t off = SW128((uint32_t)((b_row + p * 16) * 128 + ks * 32 + b_chb));
                uint32_t t0, t1, t2, t3;
                LDSM_X4(t0, t1, t2, t3, s_bhi + off);
                b_hi[2 * p][0] = t0; b_hi[2 * p][1] = t1;
                b_hi[2 * p + 1][0] = t2; b_hi[2 * p + 1][1] = t3;
                LDSM_X4(t0, t1, t2, t3, s_blo + off);
                b_lo[2 * p][0] = t0; b_lo[2 * p][1] = t1;
                b_lo[2 * p + 1][0] = t2; b_lo[2 * p + 1][1] = t3;
            }
            // three passes; 16 independent accumulators between dependent MMAs
#pragma unroll
            for (int mi = 0; mi < 2; mi++)
#pragma unroll
                for (int ni = 0; ni < 8; ni++)
                    MMA_BF16(acc[mi][ni], a_hi[mi], b_hi[ni]);
#pragma unroll
            for (int mi = 0; mi < 2; mi++)
#pragma unroll
                for (int ni = 0; ni < 8; ni++)
                    MMA_BF16(acc[mi][ni], a_hi[mi], b_lo[ni]);
#pragma unroll
            for (int mi = 0; mi < 2; mi++)
#pragma unroll
                for (int ni = 0; ni < 8; ni++)
                    MMA_BF16(acc[mi][ni], a_lo[mi], b_hi[ni]);
        }
    }

    // epilogue: registers -> gmem (8B per store, full 32B sectors per quad)
#pragma unroll
    for (int mi = 0; mi < 2; mi++) {
#pragma unroll
        for (int ni = 0; ni < 8; ni++) {
            int row = m0 + wm * 32 + mi * 16 + (lane >> 2);
            int col = n0 + wn * 64 + ni * 8 + 2 * (lane & 3);
            float2 v0 = make_float2(acc[mi][ni][0], acc[mi][ni][1]);
            float2 v1 = make_float2(acc[mi][ni][2], acc[mi][ni][3]);
            *(float2*)(out + (size_t)row * OO + col) = v0;
            *(float2*)(out + (size_t)(row + 8) * OO + col) = v1;
        }
    }
}

// ---------------- launch --------------------------------------------------
extern "C" void kernel_launch(void* const* d_in, const int* in_sizes, int n_in,
                              void* d_out, int out_size) {
    const float* x  = (const float*)d_in[0];   // [B, S, D]
    const float* A  = (const float*)d_in[1];   // [D]
    const float* BC = (const float*)d_in[2];   // [D, O]
    float* out = (float*)d_out;                // [B, S, O]
    (void)in_sizes; (void)n_in; (void)out_size;

    int scan_threads = BB * NCH * DD;          // 65536
    scan_carry_kernel<<<scan_threads / 256, 256>>>(x, A);
    scan_emit_kernel<<<scan_threads / 256, 256>>>(x, A);
    bc_transpose_split_kernel<<<dim3(OO / 32, DD / 32), dim3(32, 8)>>>(BC);

    cudaFuncSetAttribute(gemm_bf16x3_kernel,
                         cudaFuncAttributeMaxDynamicSharedMemorySize, SM_GEMM);
    dim3 grid((BB * SS) / TM, OO / TN);        // 128 x 8
    gemm_bf16x3_kernel<<<grid, 256, SM_GEMM>>>(out);
}